// round 1
// baseline (speedup 1.0000x reference)
#include <cuda_runtime.h>
#include <cstdint>
#include <cstddef>

// Problem constants
#define NB   8
#define CB   128
#define NC   1024          // NB*CB
#define HH   160
#define WW   160
#define NA   180
#define NR   180
#define AR   (NA*NR)       // 32400
#define PIX  (HH*WW)       // 25600

// Scratch in __device__ globals (no allocation allowed)
__device__ float         g_T[(size_t)AR * NC];       // transposed: T[a][r][nc], 132.7 MB
__device__ unsigned char g_idx[(size_t)NA * PIX];    // r index table [a][y][x], 4.6 MB

// ---------------------------------------------------------------------------
// Kernel 1: build rho-index table, fp64 to match numpy exactly (rint = half-even)
// ---------------------------------------------------------------------------
__global__ void build_idx_kernel()
{
    int a = blockIdx.x;
    const double PI = 3.14159265358979323846;
    double th = (double)a * (PI / 180.0);
    double irho = 227.0 / 180.0;   // (int(sqrt(160^2+160^2))+1)/180 = 227/180
    double tc = cos(th) / irho;
    double ts = sin(th) / irho;
    unsigned char* dst = g_idx + (size_t)a * PIX;
    for (int p = threadIdx.x; p < PIX; p += blockDim.x) {
        int y = p / WW, x = p - y * WW;
        double v = (double)(x - 80) * tc + (double)(y - 80) * ts;
        int r = (int)rint(v) + 90;
        r = min(NR - 1, max(0, r));
        dst[p] = (unsigned char)r;
    }
}

// ---------------------------------------------------------------------------
// Kernel 2: transpose In[NC][AR] -> T[AR][NC]
// ---------------------------------------------------------------------------
__global__ void transpose_kernel(const float* __restrict__ in)
{
    __shared__ float tile[32][33];
    int ar0 = blockIdx.x * 32;
    int nc0 = blockIdx.y * 32;
    int tx = threadIdx.x;   // 0..31
    int ty = threadIdx.y;   // 0..7
    #pragma unroll
    for (int i = ty; i < 32; i += 8) {
        int ar = ar0 + tx;
        if (ar < AR) tile[i][tx] = in[(size_t)(nc0 + i) * AR + ar];
    }
    __syncthreads();
    #pragma unroll
    for (int i = ty; i < 32; i += 8) {
        int ar = ar0 + i;
        if (ar < AR) g_T[(size_t)ar * NC + nc0 + tx] = tile[tx][i];
    }
}

// ---------------------------------------------------------------------------
// Kernel 3: main inverse-Hough accumulation
//   CTA: 16x16 pixel tile x 128-channel group. 512 threads = 16 warps.
//   Warp: 4x4 pixel subtile, lanes = 32 x 4 consecutive channels (float4/LDG.128).
//   Per angle: serpentine walk over the 4x4 subtile (x-fast when |cos|<=|sin|,
//   y-fast otherwise) so r changes rarely; reload only when r != prev.
//   Accumulate in packed f32x2 (2 packed adds per pixel, 4 channels).
// ---------------------------------------------------------------------------
__global__ void __launch_bounds__(512, 1) iht_main_kernel(float* __restrict__ out)
{
    __shared__ unsigned char sidx[NA * 256];   // [a][py(16)][px(16)] = 46080 B

    const int tid = threadIdx.x;
    const int x0 = blockIdx.x * 16;
    const int y0 = blockIdx.y * 16;
    const int c0 = blockIdx.z * 128 + (tid & 31) * 4;   // 4 channels per lane

    // Stage index tile: rows of 16 bytes, 16B-aligned (x0 % 16 == 0, strides % 16 == 0)
    for (int i = tid; i < NA * 16; i += 512) {
        int a = i >> 4, py = i & 15;
        const uint4* src = (const uint4*)(g_idx + (size_t)a * PIX + (y0 + py) * WW + x0);
        ((uint4*)sidx)[a * 16 + py] = *src;
    }
    __syncthreads();

    const int w  = tid >> 5;
    const int sy = (w >> 2) << 2;   // subtile origin within tile
    const int sx = (w & 3) << 2;

    unsigned long long acc[32];     // [pixel(py*4+px)][2] : packed ch pairs (c0,c0+1),(c0+2,c0+3)
    #pragma unroll
    for (int i = 0; i < 32; i++) acc[i] = 0ull;

    unsigned long long v0 = 0ull, v1 = 0ull;
    const unsigned char* sb = sidx + sy * 16 + sx;
    const float* __restrict__ Tb = g_T + c0;

#define STEP(OFF, AI) do {                                                  \
        int r = si[OFF];                                                    \
        if (r != prev) {                                                    \
            prev = r;                                                       \
            ulonglong2 t = *(const ulonglong2*)(base + (r << 10));          \
            v0 = t.x; v1 = t.y;                                             \
        }                                                                   \
        asm("add.rn.f32x2 %0, %0, %1;" : "+l"(acc[2*(AI)])   : "l"(v0));    \
        asm("add.rn.f32x2 %0, %0, %1;" : "+l"(acc[2*(AI)+1]) : "l"(v1));    \
    } while (0)

    for (int a = 0; a < NA; a++) {
        const float* base = Tb + (size_t)a * (NR * NC);
        const unsigned char* si = sb + a * 256;
        int prev = -1;
        if (a >= 45 && a < 135) {
            // |cos| <= |sin| : runs along x -> x-fast serpentine
            STEP(0,0);  STEP(1,1);  STEP(2,2);  STEP(3,3);
            STEP(19,7); STEP(18,6); STEP(17,5); STEP(16,4);
            STEP(32,8); STEP(33,9); STEP(34,10);STEP(35,11);
            STEP(51,15);STEP(50,14);STEP(49,13);STEP(48,12);
        } else {
            // runs along y -> y-fast serpentine
            STEP(0,0);  STEP(16,4); STEP(32,8); STEP(48,12);
            STEP(49,13);STEP(33,9); STEP(17,5); STEP(1,1);
            STEP(2,2);  STEP(18,6); STEP(34,10);STEP(50,14);
            STEP(51,15);STEP(35,11);STEP(19,7); STEP(3,3);
        }
    }
#undef STEP

    // Epilogue: per channel j, per row: float4 store over 4 consecutive x
    const int gx = x0 + sx;
    #pragma unroll
    for (int py = 0; py < 4; py++) {
        int gy = y0 + sy + py;
        float* orow = out + (size_t)gy * WW + gx;
        #pragma unroll
        for (int j = 0; j < 4; j++) {
            float4 o;
            {
                unsigned long long a0 = acc[(py*4+0)*2 + (j>>1)];
                unsigned long long a1 = acc[(py*4+1)*2 + (j>>1)];
                unsigned long long a2 = acc[(py*4+2)*2 + (j>>1)];
                unsigned long long a3 = acc[(py*4+3)*2 + (j>>1)];
                if (j & 1) {
                    o.x = __uint_as_float((unsigned)(a0 >> 32));
                    o.y = __uint_as_float((unsigned)(a1 >> 32));
                    o.z = __uint_as_float((unsigned)(a2 >> 32));
                    o.w = __uint_as_float((unsigned)(a3 >> 32));
                } else {
                    o.x = __uint_as_float((unsigned)a0);
                    o.y = __uint_as_float((unsigned)a1);
                    o.z = __uint_as_float((unsigned)a2);
                    o.w = __uint_as_float((unsigned)a3);
                }
            }
            *(float4*)(orow + (size_t)(c0 + j) * PIX) = o;
        }
    }
}

// ---------------------------------------------------------------------------
extern "C" void kernel_launch(void* const* d_in, const int* in_sizes, int n_in,
                              void* d_out, int out_size)
{
    const float* hough = (const float*)d_in[0];
    float* out = (float*)d_out;

    build_idx_kernel<<<NA, 256>>>();
    transpose_kernel<<<dim3((AR + 31) / 32, NC / 32), dim3(32, 8)>>>(hough);
    iht_main_kernel<<<dim3(10, 10, 8), 512>>>(out);
}

// round 2
// speedup vs baseline: 1.3148x; 1.3148x over previous
#include <cuda_runtime.h>
#include <cstdint>
#include <cstddef>

// Problem constants
#define NB   8
#define CB   128
#define NC   1024          // NB*CB
#define HH   160
#define WW   160
#define NA   180
#define NR   180
#define AR   (NA*NR)       // 32400
#define PIX  (HH*WW)       // 25600
#define WROWS 20           // staged rho-window (max true span is 18)

// Scratch in __device__ globals (no allocation allowed)
__device__ float         g_T[(size_t)AR * NC];       // transposed: T[a][r][nc], 132.7 MB
__device__ unsigned char g_idx[(size_t)NA * PIX];    // r index table [a][y][x], 4.6 MB

// ---------------------------------------------------------------------------
// Kernel 1: build rho-index table, fp64, matches numpy (mul,mul,add each RN;
// rint = half-even). grid (100, 180) x 256 for full occupancy.
// ---------------------------------------------------------------------------
__global__ void build_idx_kernel()
{
    __shared__ double stc, sts;
    const int a = blockIdx.y;
    if (threadIdx.x == 0) {
        const double PI = 3.14159265358979323846;
        double th = (double)a * (PI / 180.0);
        double irho = 227.0 / 180.0;   // (int(sqrt(160^2+160^2))+1)/180
        stc = cos(th) / irho;
        sts = sin(th) / irho;
    }
    __syncthreads();
    int p = blockIdx.x * 256 + threadIdx.x;
    int y = p / WW, x = p - y * WW;
    double v = __dadd_rn(__dmul_rn((double)(x - 80), stc),
                         __dmul_rn((double)(y - 80), sts));
    int r = (int)rint(v) + 90;
    r = min(NR - 1, max(0, r));
    g_idx[(size_t)a * PIX + p] = (unsigned char)r;
}

// ---------------------------------------------------------------------------
// Kernel 2: transpose In[NC][AR] -> T[AR][NC]
// ---------------------------------------------------------------------------
__global__ void transpose_kernel(const float* __restrict__ in)
{
    __shared__ float tile[32][33];
    int ar0 = blockIdx.x * 32;
    int nc0 = blockIdx.y * 32;
    int tx = threadIdx.x;   // 0..31
    int ty = threadIdx.y;   // 0..7
    #pragma unroll
    for (int i = ty; i < 32; i += 8) {
        int ar = ar0 + tx;
        if (ar < AR) tile[i][tx] = in[(size_t)(nc0 + i) * AR + ar];
    }
    __syncthreads();
    #pragma unroll
    for (int i = ty; i < 32; i += 8) {
        int ar = ar0 + i;
        if (ar < AR) g_T[(size_t)ar * NC + nc0 + tx] = tile[tx][i];
    }
}

// ---------------------------------------------------------------------------
// Kernel 3: main inverse-Hough accumulation.
//   CTA: 16x16 pixel tile x 128-ch group. 512 threads / 16 warps.
//   Warp = 4x4 pixel subtile; lanes = 32 x 4 consecutive channels.
//   Per angle: cooperative cp.async staging of rows [rmin,rmax] (<=18 rows x
//   512B of this CTA's channel slice) into a 4-deep smem pipeline; consume
//   reads via LDS.128 only on r-change along a line-direction serpentine.
// ---------------------------------------------------------------------------
__device__ __forceinline__ void cp16(unsigned smem_addr, const void* gptr)
{
    asm volatile("cp.async.cg.shared.global [%0], [%1], 16;\n"
                 :: "r"(smem_addr), "l"(gptr));
}

__global__ void __launch_bounds__(512, 1) iht_main_kernel(float* __restrict__ out)
{
    __shared__ __align__(16) char sbuf[4][WROWS * 512];   // 40960 B

    const int tid = threadIdx.x;
    const int x0 = blockIdx.x * 16;
    const int y0 = blockIdx.y * 16;
    const int cz0 = blockIdx.z * 128;
    const int lane = tid & 31;
    const int c0 = cz0 + lane * 4;          // 4 channels per lane

    // tile corner offsets inside one angle slice of g_idx
    const int o00 = y0 * WW + x0;
    const int o01 = o00 + 15;
    const int o10 = o00 + 15 * WW;
    const int o11 = o10 + 15;

    const int w  = tid >> 5;
    const int sy = (w >> 2) << 2;           // subtile origin within tile
    const int sx = (w & 3) << 2;

    // ---- staging lambda-equivalent ----
    auto stage = [&](int a3) {
        const unsigned char* s = g_idx + (size_t)a3 * PIX;
        int r00 = s[o00], r01 = s[o01], r10 = s[o10], r11 = s[o11];
        int rmin = min(min(r00, r01), min(r10, r11));
        int rmax = max(max(r00, r01), max(r10, r11));
        int base = min(rmin, NR - WROWS);
        int nch  = ((rmax - base + 1) << 5);           // 16B chunks needed
        char* dst = sbuf[a3 & 3];
        const float* src = g_T + ((size_t)a3 * NR + base) * NC + cz0;
        unsigned sdst = (unsigned)__cvta_generic_to_shared(dst);
        int c = tid;
        if (c < nch)
            cp16(sdst + (c << 4), src + ((c >> 5) << 10) + ((c & 31) << 2));
        c = tid + 512;
        if (tid < 128 && c < nch)
            cp16(sdst + (c << 4), src + ((c >> 5) << 10) + ((c & 31) << 2));
        asm volatile("cp.async.commit_group;\n" ::: "memory");
    };

    // ---- accumulators ----
    unsigned long long acc[32];
    #pragma unroll
    for (int i = 0; i < 32; i++) acc[i] = 0ull;

    // per-thread idx word pointer (4x4 block rows, one uint each)
    const unsigned* ipb = (const unsigned*)(g_idx + (y0 + sy) * WW + x0 + sx);
    const unsigned astride = PIX / 4;       // uints per angle slice

    // prologue: stage angles 0..2, preload consume-metadata for angle 0
    stage(0); stage(1); stage(2);
    unsigned iw0, iw1, iw2, iw3;
    int base;
    {
        const unsigned* ip = ipb;
        iw0 = ip[0]; iw1 = ip[40]; iw2 = ip[80]; iw3 = ip[120];
        const unsigned char* s = g_idx;
        int rmin = min(min(s[o00], s[o01]), min(s[o10], s[o11]));
        base = min(rmin, NR - WROWS);
    }

#define STEP(PX, PY) do {                                                   \
        int r = (iw##PY >> (8 * PX)) & 255;                                 \
        if (r != prev) {                                                    \
            prev = r;                                                       \
            ulonglong2 t = *(const ulonglong2*)(pv + ((unsigned)r << 9));   \
            v0 = t.x; v1 = t.y;                                             \
        }                                                                   \
        asm("add.rn.f32x2 %0, %0, %1;" : "+l"(acc[2*((PY)*4+(PX))])   : "l"(v0)); \
        asm("add.rn.f32x2 %0, %0, %1;" : "+l"(acc[2*((PY)*4+(PX))+1]) : "l"(v1)); \
    } while (0)

    #pragma unroll 1
    for (int a = 0; a < NA; a++) {
        // wait for stage(a) (3 groups in flight normally)
        if (a < 178)      asm volatile("cp.async.wait_group 2;\n" ::: "memory");
        else if (a == 178) asm volatile("cp.async.wait_group 1;\n" ::: "memory");
        else               asm volatile("cp.async.wait_group 0;\n" ::: "memory");
        __syncthreads();

        if (a + 3 < NA) stage(a + 3);

        // prefetch next angle's consume metadata
        unsigned niw0 = 0, niw1 = 0, niw2 = 0, niw3 = 0;
        int nbase = 0;
        if (a + 1 < NA) {
            const unsigned* ip = ipb + (size_t)(a + 1) * astride;
            niw0 = ip[0]; niw1 = ip[40]; niw2 = ip[80]; niw3 = ip[120];
            const unsigned char* s = g_idx + (size_t)(a + 1) * PIX;
            int rmin = min(min(s[o00], s[o01]), min(s[o10], s[o11]));
            nbase = min(rmin, NR - WROWS);
        }

        // consume angle a from smem
        const char* pv = sbuf[a & 3] + (lane << 4) - ((unsigned)base << 9);
        int prev = -1;
        unsigned long long v0 = 0ull, v1 = 0ull;

        if (a >= 23 && a <= 67) {
            // diag: r const along (+1,-1); groups of const (x+y)
            STEP(0,0); STEP(0,1); STEP(1,0); STEP(2,0); STEP(1,1); STEP(0,2);
            STEP(0,3); STEP(1,2); STEP(2,1); STEP(3,0); STEP(3,1); STEP(2,2);
            STEP(1,3); STEP(2,3); STEP(3,2); STEP(3,3);
        } else if (a >= 68 && a <= 112) {
            // x-fast serpentine
            STEP(0,0); STEP(1,0); STEP(2,0); STEP(3,0);
            STEP(3,1); STEP(2,1); STEP(1,1); STEP(0,1);
            STEP(0,2); STEP(1,2); STEP(2,2); STEP(3,2);
            STEP(3,3); STEP(2,3); STEP(1,3); STEP(0,3);
        } else if (a >= 113 && a <= 157) {
            // anti-diag: r const along (+1,+1); groups of const (x-y)
            STEP(3,0); STEP(3,1); STEP(2,0); STEP(1,0); STEP(2,1); STEP(3,2);
            STEP(3,3); STEP(2,2); STEP(1,1); STEP(0,0); STEP(0,1); STEP(1,2);
            STEP(2,3); STEP(1,3); STEP(0,2); STEP(0,3);
        } else {
            // y-fast serpentine
            STEP(0,0); STEP(0,1); STEP(0,2); STEP(0,3);
            STEP(1,3); STEP(1,2); STEP(1,1); STEP(1,0);
            STEP(2,0); STEP(2,1); STEP(2,2); STEP(2,3);
            STEP(3,3); STEP(3,2); STEP(3,1); STEP(3,0);
        }

        iw0 = niw0; iw1 = niw1; iw2 = niw2; iw3 = niw3;
        base = nbase;
    }
#undef STEP

    // Epilogue: per channel j, per row: float4 store over 4 consecutive x
    const int gx = x0 + sx;
    #pragma unroll
    for (int py = 0; py < 4; py++) {
        int gy = y0 + sy + py;
        float* orow = out + (size_t)gy * WW + gx;
        #pragma unroll
        for (int j = 0; j < 4; j++) {
            float4 o;
            {
                unsigned long long a0 = acc[(py*4+0)*2 + (j>>1)];
                unsigned long long a1 = acc[(py*4+1)*2 + (j>>1)];
                unsigned long long a2 = acc[(py*4+2)*2 + (j>>1)];
                unsigned long long a3 = acc[(py*4+3)*2 + (j>>1)];
                if (j & 1) {
                    o.x = __uint_as_float((unsigned)(a0 >> 32));
                    o.y = __uint_as_float((unsigned)(a1 >> 32));
                    o.z = __uint_as_float((unsigned)(a2 >> 32));
                    o.w = __uint_as_float((unsigned)(a3 >> 32));
                } else {
                    o.x = __uint_as_float((unsigned)a0);
                    o.y = __uint_as_float((unsigned)a1);
                    o.z = __uint_as_float((unsigned)a2);
                    o.w = __uint_as_float((unsigned)a3);
                }
            }
            *(float4*)(orow + (size_t)(c0 + j) * PIX) = o;
        }
    }
}

// ---------------------------------------------------------------------------
extern "C" void kernel_launch(void* const* d_in, const int* in_sizes, int n_in,
                              void* d_out, int out_size)
{
    const float* hough = (const float*)d_in[0];
    float* out = (float*)d_out;

    build_idx_kernel<<<dim3(PIX / 256, NA), 256>>>();
    transpose_kernel<<<dim3((AR + 31) / 32, NC / 32), dim3(32, 8)>>>(hough);
    iht_main_kernel<<<dim3(10, 10, 8), 512>>>(out);
}

// round 3
// speedup vs baseline: 1.5722x; 1.1957x over previous
#include <cuda_runtime.h>
#include <cstdint>
#include <cstddef>

// Problem constants
#define NB   8
#define CB   128
#define NC   1024          // NB*CB
#define HH   160
#define WW   160
#define NA   180
#define NR   180
#define AR   (NA*NR)       // 32400
#define PIX  (HH*WW)       // 25600
#define WROWS 20           // staged rho-window (max true span is 18)

// Scratch in __device__ globals (no allocation allowed)
__device__ float         g_T[(size_t)AR * NC];       // transposed: T[a][r][nc]
__device__ unsigned char g_idx[(size_t)NA * PIX];    // r index table [a][y][x]
__device__ double        g_tab[2 * NA];              // cos/irho, sin/irho

// ---------------------------------------------------------------------------
// Kernel 0: trig table (fp64, once) — keeps the DP sincos off the hot kernel
// ---------------------------------------------------------------------------
__global__ void tab_kernel()
{
    int a = threadIdx.x;
    if (a < NA) {
        const double PI = 3.14159265358979323846;
        double th = (double)a * (PI / 180.0);
        double irho = 227.0 / 180.0;   // (int(sqrt(160^2+160^2))+1)/180
        g_tab[a]      = cos(th) / irho;
        g_tab[NA + a] = sin(th) / irho;
    }
}

// ---------------------------------------------------------------------------
// Kernel 1: rho-index table; pure fp64 FMA-class ops (matches numpy exactly:
// mul,mul,add each RN; rint = half-even)
// ---------------------------------------------------------------------------
__global__ void build_idx_kernel()
{
    const int a = blockIdx.y;
    double tc = g_tab[a], ts = g_tab[NA + a];
    int p = blockIdx.x * 256 + threadIdx.x;
    int y = p / WW, x = p - y * WW;
    double v = __dadd_rn(__dmul_rn((double)(x - 80), tc),
                         __dmul_rn((double)(y - 80), ts));
    int r = (int)rint(v) + 90;
    r = min(NR - 1, max(0, r));
    g_idx[(size_t)a * PIX + p] = (unsigned char)r;
}

// ---------------------------------------------------------------------------
// Kernel 2: transpose In[NC][AR] -> T[AR][NC]
// ---------------------------------------------------------------------------
__global__ void transpose_kernel(const float* __restrict__ in)
{
    __shared__ float tile[32][33];
    int ar0 = blockIdx.x * 32;
    int nc0 = blockIdx.y * 32;
    int tx = threadIdx.x;
    int ty = threadIdx.y;
    #pragma unroll
    for (int i = ty; i < 32; i += 8) {
        int ar = ar0 + tx;
        if (ar < AR) tile[i][tx] = in[(size_t)(nc0 + i) * AR + ar];
    }
    __syncthreads();
    #pragma unroll
    for (int i = ty; i < 32; i += 8) {
        int ar = ar0 + i;
        if (ar < AR) g_T[(size_t)ar * NC + nc0 + tx] = tile[tx][i];
    }
}

// ---------------------------------------------------------------------------
// Kernel 3: main inverse-Hough accumulation.
//   CTA: 16x16 pixel tile x 128-ch group, 512 thr / 16 warps.
//   Warp = 4x4 pixel subtile; lanes = 32 x 4 consecutive channels.
//   idx tile staged once to smem; per-angle (base,nchunks) precomputed;
//   per angle: cp.async 4-deep pipeline stages rows [base, rmax]; consume
//   via PREDICATED @p ld.shared.v2.u64 (no branches) along line-direction
//   serpentine; accumulate packed f32x2.
// ---------------------------------------------------------------------------
__device__ __forceinline__ void cp16(unsigned smem_addr, const void* gptr)
{
    asm volatile("cp.async.cg.shared.global [%0], [%1], 16;\n"
                 :: "r"(smem_addr), "l"(gptr));
}

__global__ void __launch_bounds__(512, 1) iht_main_kernel(float* __restrict__ out)
{
    __shared__ __align__(16) char sbuf[4][WROWS * 512];          // 40960 B
    __shared__ __align__(16) unsigned char sidx[NA * 256];       // 46080 B
    __shared__ unsigned smeta[NA];                               // base | nch<<16

    const int tid = threadIdx.x;
    const int x0 = blockIdx.x * 16;
    const int y0 = blockIdx.y * 16;
    const int cz0 = blockIdx.z * 128;
    const int lane = tid & 31;
    const int c0 = cz0 + lane * 4;

    const int w  = tid >> 5;
    const int sy = (w >> 2) << 2;
    const int sx = (w & 3) << 2;

    // ---- stage idx tile to smem (16B rows, aligned) ----
    for (int i = tid; i < NA * 16; i += 512) {
        int a = i >> 4, py = i & 15;
        ((uint4*)sidx)[i] =
            *(const uint4*)(g_idx + (size_t)a * PIX + (y0 + py) * WW + x0);
    }
    __syncthreads();

    // ---- per-angle meta: base row + #16B chunks to stage ----
    for (int a = tid; a < NA; a += 512) {
        const unsigned char* s = sidx + a * 256;
        int r00 = s[0], r01 = s[15], r10 = s[240], r11 = s[255];
        int rmin = min(min(r00, r01), min(r10, r11));
        int rmax = max(max(r00, r01), max(r10, r11));
        int base = min(rmin, NR - WROWS);
        int nch  = (rmax - base + 1) << 5;
        smeta[a] = (unsigned)base | ((unsigned)nch << 16);
    }
    __syncthreads();

    // ---- staging ----
    auto stage = [&](int a3) {
        unsigned m = smeta[a3];
        int base = m & 0xffff;
        int nch  = m >> 16;
        const float* src = g_T + ((size_t)a3 * NR + base) * NC + cz0;
        unsigned sdst = (unsigned)__cvta_generic_to_shared(sbuf[a3 & 3]);
        if (tid < nch)
            cp16(sdst + (tid << 4), src + ((tid >> 5) << 10) + ((tid & 31) << 2));
        int c = tid + 512;
        if (tid < 128 && c < nch)
            cp16(sdst + (c << 4), src + ((c >> 5) << 10) + ((c & 31) << 2));
        asm volatile("cp.async.commit_group;\n" ::: "memory");
    };

    // ---- accumulators ----
    unsigned long long acc[32];
    #pragma unroll
    for (int i = 0; i < 32; i++) acc[i] = 0ull;

    const unsigned* iwp = (const unsigned*)(sidx) + sy * 4 + (sx >> 2);

    stage(0); stage(1); stage(2);

    unsigned iw0, iw1, iw2, iw3;
    int cbase;
    {
        iw0 = iwp[0]; iw1 = iwp[4]; iw2 = iwp[8]; iw3 = iwp[12];
        cbase = smeta[0] & 0xffff;
    }

#define STEP(PX, PY) do {                                                     \
        asm volatile("{\n\t"                                                  \
            ".reg .pred p;\n\t"                                               \
            ".reg .u32 rr, ad;\n\t"                                           \
            "bfe.u32 rr, %5, %6, 8;\n\t"                                      \
            "setp.ne.u32 p, rr, %4;\n\t"                                      \
            "@p mov.u32 %4, rr;\n\t"                                          \
            "@p mad.lo.u32 ad, rr, 512, %7;\n\t"                              \
            "@p ld.shared.v2.u64 {%2, %3}, [ad];\n\t"                         \
            "add.rn.f32x2 %0, %0, %2;\n\t"                                    \
            "add.rn.f32x2 %1, %1, %3;\n\t"                                    \
            "}"                                                               \
            : "+l"(acc[2*((PY)*4+(PX))]), "+l"(acc[2*((PY)*4+(PX))+1]),       \
              "+l"(v0), "+l"(v1), "+r"(prev)                                  \
            : "r"(iw##PY), "n"(8*(PX)), "r"(pvbase));                         \
    } while (0)

    #pragma unroll 1
    for (int a = 0; a < NA; a++) {
        if (a < NA - 3)       asm volatile("cp.async.wait_group 2;\n" ::: "memory");
        else if (a == NA - 3) asm volatile("cp.async.wait_group 2;\n" ::: "memory");
        else if (a == NA - 2) asm volatile("cp.async.wait_group 1;\n" ::: "memory");
        else                  asm volatile("cp.async.wait_group 0;\n" ::: "memory");
        __syncthreads();

        if (a + 3 < NA) stage(a + 3);

        // prefetch next angle's idx words + base
        unsigned niw0 = 0, niw1 = 0, niw2 = 0, niw3 = 0;
        int nbase = 0;
        if (a + 1 < NA) {
            const unsigned* ip = iwp + (a + 1) * 64;
            niw0 = ip[0]; niw1 = ip[4]; niw2 = ip[8]; niw3 = ip[12];
            nbase = smeta[a + 1] & 0xffff;
        }

        unsigned pvbase = (unsigned)__cvta_generic_to_shared(sbuf[a & 3])
                          + (lane << 4) - ((unsigned)cbase << 9);
        unsigned prev = 0xFFFFFFFFu;
        unsigned long long v0 = 0ull, v1 = 0ull;

        if (a >= 23 && a <= 67) {
            STEP(0,0); STEP(0,1); STEP(1,0); STEP(2,0); STEP(1,1); STEP(0,2);
            STEP(0,3); STEP(1,2); STEP(2,1); STEP(3,0); STEP(3,1); STEP(2,2);
            STEP(1,3); STEP(2,3); STEP(3,2); STEP(3,3);
        } else if (a >= 68 && a <= 112) {
            STEP(0,0); STEP(1,0); STEP(2,0); STEP(3,0);
            STEP(3,1); STEP(2,1); STEP(1,1); STEP(0,1);
            STEP(0,2); STEP(1,2); STEP(2,2); STEP(3,2);
            STEP(3,3); STEP(2,3); STEP(1,3); STEP(0,3);
        } else if (a >= 113 && a <= 157) {
            STEP(3,0); STEP(3,1); STEP(2,0); STEP(1,0); STEP(2,1); STEP(3,2);
            STEP(3,3); STEP(2,2); STEP(1,1); STEP(0,0); STEP(0,1); STEP(1,2);
            STEP(2,3); STEP(1,3); STEP(0,2); STEP(0,3);
        } else {
            STEP(0,0); STEP(0,1); STEP(0,2); STEP(0,3);
            STEP(1,3); STEP(1,2); STEP(1,1); STEP(1,0);
            STEP(2,0); STEP(2,1); STEP(2,2); STEP(2,3);
            STEP(3,3); STEP(3,2); STEP(3,1); STEP(3,0);
        }

        iw0 = niw0; iw1 = niw1; iw2 = niw2; iw3 = niw3;
        cbase = nbase;
    }
#undef STEP

    // ---- epilogue: float4 stores, 4 consecutive x per channel ----
    const int gx = x0 + sx;
    #pragma unroll
    for (int py = 0; py < 4; py++) {
        int gy = y0 + sy + py;
        float* orow = out + (size_t)gy * WW + gx;
        #pragma unroll
        for (int j = 0; j < 4; j++) {
            float4 o;
            unsigned long long a0 = acc[(py*4+0)*2 + (j>>1)];
            unsigned long long a1 = acc[(py*4+1)*2 + (j>>1)];
            unsigned long long a2 = acc[(py*4+2)*2 + (j>>1)];
            unsigned long long a3 = acc[(py*4+3)*2 + (j>>1)];
            if (j & 1) {
                o.x = __uint_as_float((unsigned)(a0 >> 32));
                o.y = __uint_as_float((unsigned)(a1 >> 32));
                o.z = __uint_as_float((unsigned)(a2 >> 32));
                o.w = __uint_as_float((unsigned)(a3 >> 32));
            } else {
                o.x = __uint_as_float((unsigned)a0);
                o.y = __uint_as_float((unsigned)a1);
                o.z = __uint_as_float((unsigned)a2);
                o.w = __uint_as_float((unsigned)a3);
            }
            *(float4*)(orow + (size_t)(c0 + j) * PIX) = o;
        }
    }
}

// ---------------------------------------------------------------------------
extern "C" void kernel_launch(void* const* d_in, const int* in_sizes, int n_in,
                              void* d_out, int out_size)
{
    const float* hough = (const float*)d_in[0];
    float* out = (float*)d_out;

    tab_kernel<<<1, 256>>>();
    build_idx_kernel<<<dim3(PIX / 256, NA), 256>>>();
    transpose_kernel<<<dim3((AR + 31) / 32, NC / 32), dim3(32, 8)>>>(hough);
    iht_main_kernel<<<dim3(10, 10, 8), 512>>>(out);
}